// round 9
// baseline (speedup 1.0000x reference)
#include <cuda_runtime.h>
#include <cstdint>

// Energy-distance loss, INT8 IMMA version.
//   loss = mean_b[ mean||x-y|| - 0.5 mean||x-x'|| - 0.5 mean||y-y'|| ]
// Grams via mma.sync.m16n8k32.s8.s8.s32 (exact int32 dot). Inputs quantized
// x_i8 = sat(round(x*S)), S=21 (N(0,1) data, clip ~6 sigma). Norms fp32-exact
// from original data; d2 = nx + ny - dot_int * (2/S^2); diagonal excluded
// analytically (strict upper, weight -1).

#define NPTS  512
#define DIMS  128
#define NB    128
#define NROWS 65536
#define N_CROSS_CTAS 2048
#define N_SELF_CTAS  1280
#define N_JOBS (N_CROSS_CTAS + 2 * N_SELF_CTAS)   // 4608
#define JOBS_PER_CTA 16
#define N_CTAS (N_JOBS / JOBS_PER_CTA)            // 288

#define QSCALE 21.0f
#define NEG2_INV_S2 (-2.0f / (QSCALE * QSCALE))

__device__ uint8_t g_fx[NROWS * DIMS];   // int8 bits
__device__ uint8_t g_fy[NROWS * DIMS];
__device__ float g_norm_x[NROWS];
__device__ float g_norm_y[NROWS];
__device__ float g_partials[N_JOBS];

// smem layout (bytes from 1024-aligned base)
#define OFF_A    0        // 16 KB int8 tile, 128B rows, xor-swizzled
#define OFF_B    16384
#define OFF_NX   32768
#define OFF_NY   33280
#define OFF_RED  33792
#define SMEM_REQ (1024 + 33824)

__device__ __forceinline__ uint32_t smem_u32(const void* p) {
    uint32_t a;
    asm("{ .reg .u64 t; cvta.to.shared.u64 t, %1; cvt.u32.u64 %0, t; }"
        : "=r"(a) : "l"(p));
    return a;
}

__device__ __forceinline__ int cvt_s8_sat(float x) {
    int r;
    asm("cvt.rni.sat.s8.f32 %0, %1;" : "=r"(r) : "f"(x));
    return r;
}

// ---------------------------------------------------------------------------
// Kernel 0: fp32 -> int8 quantize + exact fp32 squared norms. 8 rows/warp.
// ---------------------------------------------------------------------------
__global__ void prep_kernel(const float* __restrict__ X,
                            const float* __restrict__ Y) {
    int warp = (blockIdx.x * blockDim.x + threadIdx.x) >> 5;
    int lane = threadIdx.x & 31;
    int row8 = warp * 8;
    const float* src; uint8_t* dst; float* ndst; int r0;
    if (row8 < NROWS) { src = X; dst = g_fx; ndst = g_norm_x; r0 = row8; }
    else              { src = Y; dst = g_fy; ndst = g_norm_y; r0 = row8 - NROWS; }

    float4 v[8];
    float s[8];
#pragma unroll
    for (int k = 0; k < 8; k++) {
        v[k] = ((const float4*)(src + (size_t)(r0 + k) * DIMS))[lane];
        s[k] = v[k].x * v[k].x + v[k].y * v[k].y + v[k].z * v[k].z + v[k].w * v[k].w;
    }
#pragma unroll
    for (int k = 0; k < 8; k++) {
        int b0 = cvt_s8_sat(v[k].x * QSCALE);
        int b1 = cvt_s8_sat(v[k].y * QSCALE);
        int b2 = cvt_s8_sat(v[k].z * QSCALE);
        int b3 = cvt_s8_sat(v[k].w * QSCALE);
        unsigned packed = (b0 & 0xFF) | ((b1 & 0xFF) << 8)
                        | ((b2 & 0xFF) << 16) | ((b3 & 0xFF) << 24);
        *(unsigned*)(dst + (size_t)(r0 + k) * DIMS + lane * 4) = packed;
#pragma unroll
        for (int o = 16; o; o >>= 1) s[k] += __shfl_xor_sync(0xffffffffu, s[k], o);
        if (lane == 0) ndst[r0 + k] = s[k];
    }
}

// ---------------------------------------------------------------------------
// Kernel 1: 128x128 distance tiles via s8 IMMA (m16n8k32, s32 accum).
// 8 warps in 4(m) x 2(n); warp tile 32x64 = 2 x 8 (m16n8) x 4 k32 chunks.
// Two barriers per job; diag tiles: warps fully below diagonal skip work.
// ---------------------------------------------------------------------------
__global__ __launch_bounds__(256, 2)
void dist_kernel() {
    extern __shared__ char dyn_smem[];
    char* sm = (char*)((((uintptr_t)dyn_smem) + 1023) & ~(uintptr_t)1023);
    uint32_t sbase = smem_u32(sm);

    int tid  = threadIdx.x;
    int lane = tid & 31;
    int warp = tid >> 5;
    int wm   = warp >> 1;
    int wn   = warp & 1;

    int a_r = (lane & 7) + ((lane >> 3) & 1) * 8;
    int a_u = lane >> 4;
    int b_r = (lane & 7) + ((lane >> 4) << 3);
    int b_u = (lane >> 3) & 1;

    int j0 = blockIdx.x * JOBS_PER_CTA;
    int j1 = j0 + JOBS_PER_CTA;

    const uint8_t* prevAbase = (const uint8_t*)0;

    for (int job = j0; job < j1; job++) {
        // ---- job decode ----
        const uint8_t *Ap, *Bp;
        const float *nAp, *nBp;
        int b, tr, tc;
        bool selfm;
        if (job < N_CROSS_CTAS) {
            b = job >> 4;
            int t = job & 15;
            tr = t >> 2; tc = t & 3;
            Ap = g_fx; Bp = g_fy; nAp = g_norm_x; nBp = g_norm_y;
            selfm = false;
        } else {
            int r = job - N_CROSS_CTAS;
            int isY = (r >= N_SELF_CTAS);
            if (isY) r -= N_SELF_CTAS;
            b = r / 10;
            int t = r - b * 10;
            int trr = 0, tt = t;
            while (tt >= 4 - trr) { tt -= 4 - trr; trr++; }
            tr = trr; tc = trr + tt;
            Ap = isY ? g_fy : g_fx;
            Bp = Ap;
            nAp = isY ? g_norm_y : g_norm_x;
            nBp = nAp;
            selfm = true;
        }
        bool diag = selfm && (tr == tc);
        const uint8_t* Abase = Ap + ((size_t)b * NPTS + tr * 128) * DIMS;
        const uint8_t* Bbase = Bp + ((size_t)b * NPTS + tc * 128) * DIMS;
        bool reuseA = (Abase == prevAbase);
        prevAbase = Abase;

        // (no leading barrier: the reduction barrier of the previous job
        //  already proved every thread finished reading smem)

        // ---- stage via cp.async ----
#pragma unroll
        for (int q = 0; q < 4; q++) {
            int idx = tid + q * 256;
            int r = idx >> 3, u = idx & 7;
            int soff = r * 128 + ((u ^ (r & 7)) << 4);
            asm volatile("cp.async.cg.shared.global [%0], [%1], 16;"
                         :: "r"(sbase + OFF_B + soff),
                            "l"((const void*)(Bbase + (size_t)r * DIMS + u * 16)));
            if (!reuseA)
                asm volatile("cp.async.cg.shared.global [%0], [%1], 16;"
                             :: "r"(sbase + OFF_A + soff),
                                "l"((const void*)(Abase + (size_t)r * DIMS + u * 16)));
        }
        if (tid < 128) {
            if (!reuseA)
                *(float*)(sm + OFF_NX + tid * 4) = nAp[b * NPTS + tr * 128 + tid];
        } else {
            *(float*)(sm + OFF_NY + (tid - 128) * 4) = nBp[b * NPTS + tc * 128 + tid - 128];
        }
        asm volatile("cp.async.commit_group;");
        asm volatile("cp.async.wait_group 0;" ::: "memory");
        __syncthreads();

        float tsum = 0.f;

        // Diagonal tiles: warps whose whole 32x64 block is strictly below
        // the diagonal (rows >= 64, cols < 64) produce all-zero -> skip.
        bool skip = diag && (wn == 0) && (wm >= 2);
        if (!skip) {
            // ---- mainloop: 4 k32 chunks, s32 accumulators ----
            int acc[2][8][4];
#pragma unroll
            for (int mt = 0; mt < 2; mt++)
#pragma unroll
                for (int nt = 0; nt < 8; nt++)
#pragma unroll
                    for (int c = 0; c < 4; c++) acc[mt][nt][c] = 0;

            uint32_t sA = sbase + OFF_A;
            uint32_t sB = sbase + OFF_B;

#pragma unroll
            for (int kk = 0; kk < 4; kk++) {
                unsigned af[2][4];
#pragma unroll
                for (int mt = 0; mt < 2; mt++) {
                    int r = wm * 32 + mt * 16 + a_r;
                    int u = kk * 2 + a_u;
                    unsigned addr = sA + (unsigned)(r * 128 + ((u ^ (r & 7)) << 4));
                    asm volatile(
                        "ldmatrix.sync.aligned.m8n8.x4.shared.b16 {%0,%1,%2,%3}, [%4];"
                        : "=r"(af[mt][0]), "=r"(af[mt][1]), "=r"(af[mt][2]), "=r"(af[mt][3])
                        : "r"(addr));
                }
#pragma unroll
                for (int pp = 0; pp < 4; pp++) {
                    int r = wn * 64 + pp * 16 + b_r;
                    int u = kk * 2 + b_u;
                    unsigned addr = sB + (unsigned)(r * 128 + ((u ^ (r & 7)) << 4));
                    unsigned bf[4];
                    asm volatile(
                        "ldmatrix.sync.aligned.m8n8.x4.shared.b16 {%0,%1,%2,%3}, [%4];"
                        : "=r"(bf[0]), "=r"(bf[1]), "=r"(bf[2]), "=r"(bf[3])
                        : "r"(addr));
#pragma unroll
                    for (int mt = 0; mt < 2; mt++) {
                        asm volatile(
                            "mma.sync.aligned.m16n8k32.row.col.s32.s8.s8.s32 "
                            "{%0,%1,%2,%3}, {%4,%5,%6,%7}, {%8,%9}, {%0,%1,%2,%3};"
                            : "+r"(acc[mt][2*pp][0]), "+r"(acc[mt][2*pp][1]),
                              "+r"(acc[mt][2*pp][2]), "+r"(acc[mt][2*pp][3])
                            : "r"(af[mt][0]), "r"(af[mt][1]), "r"(af[mt][2]), "r"(af[mt][3]),
                              "r"(bf[0]), "r"(bf[1]));
                        asm volatile(
                            "mma.sync.aligned.m16n8k32.row.col.s32.s8.s8.s32 "
                            "{%0,%1,%2,%3}, {%4,%5,%6,%7}, {%8,%9}, {%0,%1,%2,%3};"
                            : "+r"(acc[mt][2*pp+1][0]), "+r"(acc[mt][2*pp+1][1]),
                              "+r"(acc[mt][2*pp+1][2]), "+r"(acc[mt][2*pp+1][3])
                            : "r"(af[mt][0]), "r"(af[mt][1]), "r"(af[mt][2]), "r"(af[mt][3]),
                              "r"(bf[2]), "r"(bf[3]));
                    }
                }
            }

            // ---- epilogue ----
            int g  = lane >> 2;
            int ct = lane & 3;

            float nx[2][2];
#pragma unroll
            for (int mt = 0; mt < 2; mt++) {
                int r0 = wm * 32 + mt * 16 + g;
                nx[mt][0] = *(const float*)(sm + OFF_NX + r0 * 4);
                nx[mt][1] = *(const float*)(sm + OFF_NX + (r0 + 8) * 4);
            }
            float ny[8][2];
#pragma unroll
            for (int nt = 0; nt < 8; nt++) {
                int c0 = wn * 64 + nt * 8 + 2 * ct;
                ny[nt][0] = *(const float*)(sm + OFF_NY + c0 * 4);
                ny[nt][1] = *(const float*)(sm + OFF_NY + (c0 + 1) * 4);
            }

            float ts0 = 0.f, ts1 = 0.f;
            if (diag) {
#pragma unroll
                for (int mt = 0; mt < 2; mt++)
#pragma unroll
                    for (int nt = 0; nt < 8; nt++)
#pragma unroll
                        for (int c = 0; c < 4; c++) {
                            int ri = c >> 1, cj = c & 1;
                            int irow = wm * 32 + mt * 16 + g + ri * 8;
                            int jcol = wn * 64 + nt * 8 + 2 * ct + cj;
                            float dotf = __int2float_rn(acc[mt][nt][c]);
                            float d2 = fmaf(dotf, NEG2_INV_S2, nx[mt][ri]) + ny[nt][cj];
                            d2 = fmaxf(d2, 0.f);
                            float dd;
                            asm("sqrt.approx.f32 %0, %1;" : "=f"(dd) : "f"(d2));
                            if (jcol <= irow) dd = 0.f;
                            if (c & 1) ts1 += dd; else ts0 += dd;
                        }
            } else {
#pragma unroll
                for (int mt = 0; mt < 2; mt++)
#pragma unroll
                    for (int nt = 0; nt < 8; nt++)
#pragma unroll
                        for (int c = 0; c < 4; c++) {
                            float dotf = __int2float_rn(acc[mt][nt][c]);
                            float d2 = fmaf(dotf, NEG2_INV_S2, nx[mt][c >> 1]) + ny[nt][c & 1];
                            d2 = fmaxf(d2, 0.f);
                            float dd;
                            asm("sqrt.approx.f32 %0, %1;" : "=f"(dd) : "f"(d2));
                            if (c & 1) ts1 += dd; else ts0 += dd;
                        }
            }
            tsum = ts0 + ts1;
#pragma unroll
            for (int o = 16; o; o >>= 1) tsum += __shfl_xor_sync(0xffffffffu, tsum, o);
        }

        if (lane == 0) *(float*)(sm + OFF_RED + warp * 4) = tsum;
        __syncthreads();     // also licenses smem overwrite by next job
        if (tid == 0) {
            float s = 0.f;
#pragma unroll
            for (int w = 0; w < 8; w++) s += *(float*)(sm + OFF_RED + w * 4);
            g_partials[job] = s;
        }
    }
}

// ---------------------------------------------------------------------------
// Kernel 2: deterministic double-precision finalize.
// ---------------------------------------------------------------------------
__global__ void finalize_kernel(float* __restrict__ out) {
    __shared__ double sd[256];
    int tid = threadIdx.x;
    double s = 0.0;
    for (int i = tid; i < N_JOBS; i += 256) {
        double v = (double)g_partials[i];
        s += (i < N_CROSS_CTAS) ? v : -v;
    }
    sd[tid] = s;
    __syncthreads();
    for (int o = 128; o; o >>= 1) {
        if (tid < o) sd[tid] += sd[tid + o];
        __syncthreads();
    }
    if (tid == 0)
        out[0] = (float)(sd[0] / ((double)NB * NPTS * NPTS));
}

// ---------------------------------------------------------------------------
extern "C" void kernel_launch(void* const* d_in, const int* in_sizes, int n_in,
                              void* d_out, int out_size) {
    const float* X = (const float*)d_in[0];
    const float* Y = (const float*)d_in[1];

    cudaFuncSetAttribute(dist_kernel,
                         cudaFuncAttributeMaxDynamicSharedMemorySize, SMEM_REQ);

    prep_kernel<<<2048, 256>>>(X, Y);
    dist_kernel<<<N_CTAS, 256, SMEM_REQ>>>();
    finalize_kernel<<<1, 256>>>((float*)d_out);
}

// round 10
// speedup vs baseline: 1.8508x; 1.8508x over previous
#include <cuda_runtime.h>
#include <cuda_bf16.h>
#include <cuda_fp8.h>
#include <cstdint>

// Energy-distance loss, FP8 QMMA f32-acc (legacy-tensor ceiling: 512 MAC/cyc/SM).
//   loss = mean_b[ mean||x-y|| - 0.5 mean||x-x'|| - 0.5 mean||y-y'|| ]
// R10 = R5 skeleton + two R9-verified wins: 2 barriers/job, diagonal warp skip.

#define NPTS  512
#define DIMS  128
#define NB    128
#define NROWS 65536
#define N_CROSS_CTAS 2048
#define N_SELF_CTAS  1280
#define N_JOBS (N_CROSS_CTAS + 2 * N_SELF_CTAS)   // 4608
#define JOBS_PER_CTA 16
#define N_CTAS (N_JOBS / JOBS_PER_CTA)            // 288

__device__ uint8_t g_fx[NROWS * DIMS];   // e4m3
__device__ uint8_t g_fy[NROWS * DIMS];
__device__ float g_norm_x[NROWS];
__device__ float g_norm_y[NROWS];
__device__ float g_partials[N_JOBS];

// smem layout (bytes from 1024-aligned base)
#define OFF_A    0        // 16 KB fp8 tile, 128B rows, xor-swizzled
#define OFF_B    16384
#define OFF_NX   32768
#define OFF_NY   33280
#define OFF_RED  33792
#define SMEM_REQ (1024 + 33824)

__device__ __forceinline__ uint32_t smem_u32(const void* p) {
    uint32_t a;
    asm("{ .reg .u64 t; cvta.to.shared.u64 t, %1; cvt.u32.u64 %0, t; }"
        : "=r"(a) : "l"(p));
    return a;
}

// ---------------------------------------------------------------------------
// Kernel 0: fp32 -> e4m3 convert + exact fp32 squared norms. 8 rows/warp.
// ---------------------------------------------------------------------------
__global__ void prep_kernel(const float* __restrict__ X,
                            const float* __restrict__ Y) {
    int warp = (blockIdx.x * blockDim.x + threadIdx.x) >> 5;
    int lane = threadIdx.x & 31;
    int row8 = warp * 8;
    const float* src; uint8_t* dst; float* ndst; int r0;
    if (row8 < NROWS) { src = X; dst = g_fx; ndst = g_norm_x; r0 = row8; }
    else              { src = Y; dst = g_fy; ndst = g_norm_y; r0 = row8 - NROWS; }

    float4 v[8];
    float s[8];
#pragma unroll
    for (int k = 0; k < 8; k++) {
        v[k] = ((const float4*)(src + (size_t)(r0 + k) * DIMS))[lane];
        s[k] = v[k].x * v[k].x + v[k].y * v[k].y + v[k].z * v[k].z + v[k].w * v[k].w;
    }
#pragma unroll
    for (int k = 0; k < 8; k++) {
        float2 lo = make_float2(v[k].x, v[k].y);
        float2 hi = make_float2(v[k].z, v[k].w);
        unsigned p0 = __nv_cvt_float2_to_fp8x2(lo, __NV_SATFINITE, __NV_E4M3);
        unsigned p1 = __nv_cvt_float2_to_fp8x2(hi, __NV_SATFINITE, __NV_E4M3);
        *(unsigned*)(dst + (size_t)(r0 + k) * DIMS + lane * 4) =
            (p0 & 0xffffu) | (p1 << 16);
#pragma unroll
        for (int o = 16; o; o >>= 1) s[k] += __shfl_xor_sync(0xffffffffu, s[k], o);
        if (lane == 0) ndst[r0 + k] = s[k];
    }
}

// ---------------------------------------------------------------------------
// Kernel 1: 128x128 distance tiles via e4m3 QMMA (m16n8k32, f32 accum).
// 8 warps in 4(m) x 2(n); warp tile 32x64. Two barriers/job; diag skip.
// ---------------------------------------------------------------------------
__global__ __launch_bounds__(256, 2)
void dist_kernel() {
    extern __shared__ char dyn_smem[];
    char* sm = (char*)((((uintptr_t)dyn_smem) + 1023) & ~(uintptr_t)1023);
    uint32_t sbase = smem_u32(sm);

    int tid  = threadIdx.x;
    int lane = tid & 31;
    int warp = tid >> 5;
    int wm   = warp >> 1;
    int wn   = warp & 1;

    int a_r = (lane & 7) + ((lane >> 3) & 1) * 8;
    int a_u = lane >> 4;
    int b_r = (lane & 7) + ((lane >> 4) << 3);
    int b_u = (lane >> 3) & 1;

    int j0 = blockIdx.x * JOBS_PER_CTA;
    int j1 = j0 + JOBS_PER_CTA;

    const uint8_t* prevAbase = (const uint8_t*)0;

    for (int job = j0; job < j1; job++) {
        // ---- job decode ----
        const uint8_t *Ap, *Bp;
        const float *nAp, *nBp;
        int b, tr, tc;
        bool selfm;
        if (job < N_CROSS_CTAS) {
            b = job >> 4;
            int t = job & 15;
            tr = t >> 2; tc = t & 3;
            Ap = g_fx; Bp = g_fy; nAp = g_norm_x; nBp = g_norm_y;
            selfm = false;
        } else {
            int r = job - N_CROSS_CTAS;
            int isY = (r >= N_SELF_CTAS);
            if (isY) r -= N_SELF_CTAS;
            b = r / 10;
            int t = r - b * 10;
            int trr = 0, tt = t;
            while (tt >= 4 - trr) { tt -= 4 - trr; trr++; }
            tr = trr; tc = trr + tt;
            Ap = isY ? g_fy : g_fx;
            Bp = Ap;
            nAp = isY ? g_norm_y : g_norm_x;
            nBp = nAp;
            selfm = true;
        }
        bool diag = selfm && (tr == tc);
        const uint8_t* Abase = Ap + ((size_t)b * NPTS + tr * 128) * DIMS;
        const uint8_t* Bbase = Bp + ((size_t)b * NPTS + tc * 128) * DIMS;
        bool reuseA = (Abase == prevAbase);
        prevAbase = Abase;

        // (no leading barrier: previous job's reduction barrier already
        //  proved all threads finished reading smem — verified in R9)

        // ---- stage via cp.async ----
#pragma unroll
        for (int q = 0; q < 4; q++) {
            int idx = tid + q * 256;
            int r = idx >> 3, u = idx & 7;
            int soff = r * 128 + ((u ^ (r & 7)) << 4);
            asm volatile("cp.async.cg.shared.global [%0], [%1], 16;"
                         :: "r"(sbase + OFF_B + soff),
                            "l"((const void*)(Bbase + (size_t)r * DIMS + u * 16)));
            if (!reuseA)
                asm volatile("cp.async.cg.shared.global [%0], [%1], 16;"
                             :: "r"(sbase + OFF_A + soff),
                                "l"((const void*)(Abase + (size_t)r * DIMS + u * 16)));
        }
        if (tid < 128) {
            if (!reuseA)
                *(float*)(sm + OFF_NX + tid * 4) = nAp[b * NPTS + tr * 128 + tid];
        } else {
            *(float*)(sm + OFF_NY + (tid - 128) * 4) = nBp[b * NPTS + tc * 128 + tid - 128];
        }
        asm volatile("cp.async.commit_group;");
        asm volatile("cp.async.wait_group 0;" ::: "memory");
        __syncthreads();

        float tsum = 0.f;

        // Diagonal tiles: warps whose whole 32x64 block is strictly below
        // the diagonal (rows >= 64, cols < 64) are all-masked -> skip.
        bool skip = diag && (wn == 0) && (wm >= 2);
        if (!skip) {
            // ---- mainloop: 4 k32 chunks, f32 accumulators ----
            float acc[2][8][4];
#pragma unroll
            for (int mt = 0; mt < 2; mt++)
#pragma unroll
                for (int nt = 0; nt < 8; nt++)
#pragma unroll
                    for (int c = 0; c < 4; c++) acc[mt][nt][c] = 0.f;

            uint32_t sA = sbase + OFF_A;
            uint32_t sB = sbase + OFF_B;

#pragma unroll
            for (int kk = 0; kk < 4; kk++) {
                unsigned af[2][4];
#pragma unroll
                for (int mt = 0; mt < 2; mt++) {
                    int r = wm * 32 + mt * 16 + a_r;
                    int u = kk * 2 + a_u;
                    unsigned addr = sA + (unsigned)(r * 128 + ((u ^ (r & 7)) << 4));
                    asm volatile(
                        "ldmatrix.sync.aligned.m8n8.x4.shared.b16 {%0,%1,%2,%3}, [%4];"
                        : "=r"(af[mt][0]), "=r"(af[mt][1]), "=r"(af[mt][2]), "=r"(af[mt][3])
                        : "r"(addr));
                }
#pragma unroll
                for (int pp = 0; pp < 4; pp++) {
                    int r = wn * 64 + pp * 16 + b_r;
                    int u = kk * 2 + b_u;
                    unsigned addr = sB + (unsigned)(r * 128 + ((u ^ (r & 7)) << 4));
                    unsigned bf[4];
                    asm volatile(
                        "ldmatrix.sync.aligned.m8n8.x4.shared.b16 {%0,%1,%2,%3}, [%4];"
                        : "=r"(bf[0]), "=r"(bf[1]), "=r"(bf[2]), "=r"(bf[3])
                        : "r"(addr));
#pragma unroll
                    for (int mt = 0; mt < 2; mt++) {
                        asm volatile(
                            "mma.sync.aligned.m16n8k32.row.col.f32.e4m3.e4m3.f32 "
                            "{%0,%1,%2,%3}, {%4,%5,%6,%7}, {%8,%9}, {%0,%1,%2,%3};"
                            : "+f"(acc[mt][2*pp][0]), "+f"(acc[mt][2*pp][1]),
                              "+f"(acc[mt][2*pp][2]), "+f"(acc[mt][2*pp][3])
                            : "r"(af[mt][0]), "r"(af[mt][1]), "r"(af[mt][2]), "r"(af[mt][3]),
                              "r"(bf[0]), "r"(bf[1]));
                        asm volatile(
                            "mma.sync.aligned.m16n8k32.row.col.f32.e4m3.e4m3.f32 "
                            "{%0,%1,%2,%3}, {%4,%5,%6,%7}, {%8,%9}, {%0,%1,%2,%3};"
                            : "+f"(acc[mt][2*pp+1][0]), "+f"(acc[mt][2*pp+1][1]),
                              "+f"(acc[mt][2*pp+1][2]), "+f"(acc[mt][2*pp+1][3])
                            : "r"(af[mt][0]), "r"(af[mt][1]), "r"(af[mt][2]), "r"(af[mt][3]),
                              "r"(bf[2]), "r"(bf[3]));
                    }
                }
            }

            // ---- epilogue ----
            int g  = lane >> 2;
            int ct = lane & 3;

            float nx[2][2];
#pragma unroll
            for (int mt = 0; mt < 2; mt++) {
                int r0 = wm * 32 + mt * 16 + g;
                nx[mt][0] = *(const float*)(sm + OFF_NX + r0 * 4);
                nx[mt][1] = *(const float*)(sm + OFF_NX + (r0 + 8) * 4);
            }
            float ny[8][2];
#pragma unroll
            for (int nt = 0; nt < 8; nt++) {
                int c0 = wn * 64 + nt * 8 + 2 * ct;
                ny[nt][0] = *(const float*)(sm + OFF_NY + c0 * 4);
                ny[nt][1] = *(const float*)(sm + OFF_NY + (c0 + 1) * 4);
            }

            float ts0 = 0.f, ts1 = 0.f;
            if (diag) {
#pragma unroll
                for (int mt = 0; mt < 2; mt++)
#pragma unroll
                    for (int nt = 0; nt < 8; nt++)
#pragma unroll
                        for (int c = 0; c < 4; c++) {
                            int ri = c >> 1, cj = c & 1;
                            int irow = wm * 32 + mt * 16 + g + ri * 8;
                            int jcol = wn * 64 + nt * 8 + 2 * ct + cj;
                            float d2 = fmaf(acc[mt][nt][c], -2.f, nx[mt][ri]) + ny[nt][cj];
                            d2 = fmaxf(d2, 0.f);
                            float dd;
                            asm("sqrt.approx.f32 %0, %1;" : "=f"(dd) : "f"(d2));
                            if (jcol <= irow) dd = 0.f;
                            if (c & 1) ts1 += dd; else ts0 += dd;
                        }
            } else {
#pragma unroll
                for (int mt = 0; mt < 2; mt++)
#pragma unroll
                    for (int nt = 0; nt < 8; nt++)
#pragma unroll
                        for (int c = 0; c < 4; c++) {
                            float d2 = fmaf(acc[mt][nt][c], -2.f, nx[mt][c >> 1]) + ny[nt][c & 1];
                            d2 = fmaxf(d2, 0.f);
                            float dd;
                            asm("sqrt.approx.f32 %0, %1;" : "=f"(dd) : "f"(d2));
                            if (c & 1) ts1 += dd; else ts0 += dd;
                        }
            }
            tsum = ts0 + ts1;
#pragma unroll
            for (int o = 16; o; o >>= 1) tsum += __shfl_xor_sync(0xffffffffu, tsum, o);
        }

        if (lane == 0) *(float*)(sm + OFF_RED + warp * 4) = tsum;
        __syncthreads();     // also licenses smem overwrite by next job
        if (tid == 0) {
            float s = 0.f;
#pragma unroll
            for (int w = 0; w < 8; w++) s += *(float*)(sm + OFF_RED + w * 4);
            g_partials[job] = s;
        }
    }
}

// ---------------------------------------------------------------------------
// Kernel 2: deterministic double-precision finalize.
// ---------------------------------------------------------------------------
__global__ void finalize_kernel(float* __restrict__ out) {
    __shared__ double sd[256];
    int tid = threadIdx.x;
    double s = 0.0;
    for (int i = tid; i < N_JOBS; i += 256) {
        double v = (double)g_partials[i];
        s += (i < N_CROSS_CTAS) ? v : -v;
    }
    sd[tid] = s;
    __syncthreads();
    for (int o = 128; o; o >>= 1) {
        if (tid < o) sd[tid] += sd[tid + o];
        __syncthreads();
    }
    if (tid == 0)
        out[0] = (float)(sd[0] / ((double)NB * NPTS * NPTS));
}

// ---------------------------------------------------------------------------
extern "C" void kernel_launch(void* const* d_in, const int* in_sizes, int n_in,
                              void* d_out, int out_size) {
    const float* X = (const float*)d_in[0];
    const float* Y = (const float*)d_in[1];

    cudaFuncSetAttribute(dist_kernel,
                         cudaFuncAttributeMaxDynamicSharedMemorySize, SMEM_REQ);

    prep_kernel<<<2048, 256>>>(X, Y);
    dist_kernel<<<N_CTAS, 256, SMEM_REQ>>>();
    finalize_kernel<<<1, 256>>>((float*)d_out);
}